// round 16
// baseline (speedup 1.0000x reference)
#include <cuda_runtime.h>
#include <math.h>

// Problem constants
#define NN     512
#define HID    1024
#define OUTD   131328          // N + N*(N-1)/2
#define OUT4   (OUTD / 4)      // 32832 float4 columns
#define KB_N   129             // gemv kb blocks
#define SPLITK 8
#define JCH    (HID / SPLITK)  // 128 rows of Wo per k-chunk
#define SI     16              // i-splits in fused MLP
#define MB     512             // blocks in fused MLP kernel (32 colgroups x SI)
#define GT     136             // lower-triangle 32x32 tiles (16*17/2)
#define PF     6               // L2-prefetch lines of Wo per MLP thread

// Device scratch (no allocation allowed). Referenced ONLY in device code.
__device__ float g_hp[3][SI][HID];       // per-layer split-i partials
__device__ float g_part[SPLITK][OUTD];   // split-K partial sums of big GEMV
__device__ float g_L[NN * NN];           // zero-init; upper tri NEVER written
__device__ unsigned g_ctr[KB_N];         // per-kb arrival counters (self-reset)

// ---------------------------------------------------------------------------
// Software grid barrier (sense-reversal) — used ONLY by the 512-block MLP.
// ---------------------------------------------------------------------------
__device__ unsigned g_bar_ctr = 0;
__device__ volatile unsigned g_bar_gen = 0;

__device__ __forceinline__ void grid_barrier(unsigned nblocks) {
    __threadfence();
    __syncthreads();
    if (threadIdx.x == 0) {
        unsigned gen = g_bar_gen;
        if (atomicAdd(&g_bar_ctr, 1) == nblocks - 1) {
            g_bar_ctr = 0;
            __threadfence();
            g_bar_gen = gen + 1;
        } else {
            while (g_bar_gen == gen) __nanosleep(32);
        }
        __threadfence();
    }
    __syncthreads();
}

// ---------------------------------------------------------------------------
// Fused 3-layer MLP + L2 pre-stream of Wo's head (round-13 proven: 104.5us).
// ---------------------------------------------------------------------------
template <int IN>
__device__ __forceinline__ void mlp_partial(
    const float* __restrict__ xs, const float* __restrict__ W,
    int cg, int isp, float* __restrict__ outp, float sh[8][32]) {
    const int CHUNK = IN / SI;
    const int CH    = CHUNK / 8;
    const int lane  = threadIdx.x & 31;
    const int w     = threadIdx.x >> 5;
    const int j     = cg * 32 + lane;
    const int base  = isp * CHUNK;
    const int i0    = w * CH;

    float acc = 0.f;
#pragma unroll
    for (int i = 0; i < CH; ++i) {
        acc += xs[i0 + i] * __ldg(&W[(size_t)(base + i0 + i) * 1024 + j]);
    }
    sh[w][lane] = acc;
    __syncthreads();
    if (w == 0) {
        float s = 0.f;
#pragma unroll
        for (int q = 0; q < 8; ++q) s += sh[q][lane];
        outp[j] = s;
    }
    __syncthreads();
}

__global__ void __launch_bounds__(256)
mlp_all(const float* __restrict__ x,
        const float* __restrict__ W0, const float* __restrict__ b0,
        const float* __restrict__ W1, const float* __restrict__ b1,
        const float* __restrict__ W2, const float* __restrict__ Wo) {
    __shared__ float sh[8][32];
    __shared__ float xs[HID / SI];

    const int cg  = blockIdx.x & 31;
    const int isp = blockIdx.x >> 5;

    // Pre-stream head of Wo into L2 (rides idle DRAM BW; ~100MB).
    {
        const size_t tg = (size_t)blockIdx.x * 256 + threadIdx.x;
#pragma unroll
        for (int p = 0; p < PF; ++p) {
            const float* a = Wo + (tg * PF + p) * 32;
            asm volatile("prefetch.global.L2 [%0];" :: "l"(a));
        }
    }

    // ---- layer 0: IN=512 ----
    {
        const int CHUNK = 512 / SI;
        for (int t = threadIdx.x; t < CHUNK; t += 256) xs[t] = x[isp * CHUNK + t];
        __syncthreads();
        mlp_partial<512>(xs, W0, cg, isp, g_hp[0][isp], sh);
    }
    grid_barrier(MB);

    // ---- layer 1: IN=1024 ----
    {
        const int CHUNK = HID / SI;
        for (int t = threadIdx.x; t < CHUNK; t += 256) {
            const int g = isp * CHUNK + t;
            float s = __ldg(&b0[g]);
#pragma unroll
            for (int q = 0; q < SI; ++q) s += g_hp[0][q][g];
            xs[t] = tanhf(s);
        }
        __syncthreads();
        mlp_partial<1024>(xs, W1, cg, isp, g_hp[1][isp], sh);
    }
    grid_barrier(MB);

    // ---- layer 2: IN=1024 ----
    {
        const int CHUNK = HID / SI;
        for (int t = threadIdx.x; t < CHUNK; t += 256) {
            const int g = isp * CHUNK + t;
            float s = __ldg(&b1[g]);
#pragma unroll
            for (int q = 0; q < SI; ++q) s += g_hp[1][q][g];
            xs[t] = tanhf(s);
        }
        __syncthreads();
        mlp_partial<1024>(xs, W2, cg, isp, g_hp[2][isp], sh);
    }
}

// ---------------------------------------------------------------------------
// Big GEMV, split-K (proven core) + L-building epilogue.
// The 8 blocks sharing kb count arrivals; the LAST one reduces the 8 partials
// + bo for its 1024 k-values and scatter-writes L (coalesced within rows).
// Values are deterministic (fixed summation order); only the executor varies.
// ---------------------------------------------------------------------------
__global__ void gemv_out(const float* __restrict__ Wo,
                         const float* __restrict__ b2,
                         const float* __restrict__ bo) {
    __shared__ float hs[JCH];
    __shared__ unsigned s_old;

    const int chunk = blockIdx.y;
    const int kb    = blockIdx.x;
    const int t     = threadIdx.x;

    if (t < JCH) {
        const int g = chunk * JCH + t;
        float s = __ldg(&b2[g]);
#pragma unroll
        for (int q = 0; q < SI; ++q) s += g_hp[2][q][g];
        hs[t] = tanhf(s);
    }
    __syncthreads();

    const int k4 = kb * 256 + t;
    const bool valid = (k4 < OUT4);

    if (valid) {
        const float4* W4 = (const float4*)Wo + (size_t)chunk * JCH * OUT4;
        float ax = 0.f, ay = 0.f, az = 0.f, aw = 0.f;
#pragma unroll 8
        for (int j = 0; j < JCH; ++j) {
            float4 wv = __ldcs(&W4[(size_t)j * OUT4 + k4]);
            float  hj = hs[j];
            ax += hj * wv.x;
            ay += hj * wv.y;
            az += hj * wv.z;
            aw += hj * wv.w;
        }
        float4 r; r.x = ax; r.y = ay; r.z = az; r.w = aw;
        ((float4*)g_part[chunk])[k4] = r;
    }

    // -------- epilogue: last arriving chunk-block builds this kb's L part ----
    __threadfence();                     // release our partial stores
    __syncthreads();
    if (t == 0) s_old = atomicAdd(&g_ctr[kb], 1);
    __syncthreads();
    if (s_old != SPLITK - 1) return;

    __threadfence();                     // acquire peers' partial stores
    if (valid) {
        float4 s = __ldg(&((const float4*)bo)[k4]);
#pragma unroll
        for (int q = 0; q < SPLITK; ++q) {
            float4 p = ((const float4*)g_part[q])[k4];
            s.x += p.x; s.y += p.y; s.z += p.z; s.w += p.w;
        }
        const int kbase = k4 * 4;
        float v[4] = {s.x, s.y, s.z, s.w};
#pragma unroll
        for (int e = 0; e < 4; ++e) {
            const int k = kbase + e;
            if (k < NN) {
                g_L[k * NN + k] = expf(v[e]);
            } else {
                const int m = k - NN;
                int r = (int)((sqrtf(8.f * m + 1.f) + 1.f) * 0.5f);
                while (r * (r - 1) / 2 > m) --r;
                while ((r + 1) * r / 2 <= m) ++r;
                const int c = m - r * (r - 1) / 2;
                g_L[r * NN + c] = v[e];
            }
        }
    }
    __syncthreads();
    if (t == 0) g_ctr[kb] = 0;           // self-reset for the next replay
}

// ---------------------------------------------------------------------------
// Pure GEMM: D = L * L^T. No phase A, no grid barrier (kernel boundary is the
// sync; L was built by gemv's epilogue; upper tri is pristine zero-init).
// grid = GT=136 lower-triangle tiles, block = 512, triangular-k.
// ---------------------------------------------------------------------------
__global__ void __launch_bounds__(512)
gemm_llt(float* __restrict__ D) {
    __shared__ float SAB[2][64][36];   // As/Bs; reduction buffer overlaid

    const int b = blockIdx.x;
    const int t = threadIdx.x;         // 0..511

    // linear block id -> (bi, bj), bj <= bi
    int bi = (int)((sqrtf(8.f * b + 1.f) - 1.f) * 0.5f);
    while ((bi + 1) * (bi + 2) / 2 <= b) ++bi;
    while (bi * (bi + 1) / 2 > b) --bi;
    const int bj = b - bi * (bi + 1) / 2;

    float (*As)[36] = SAB[0];
    float (*Bs)[36] = SAB[1];

    const int grp  = t >> 6;              // 0..7: k-groups of 8
    const int id64 = t & 63;
    const int tx   = id64 & 7;
    const int ty   = id64 >> 3;

    const int lr = t >> 4;                // 0..31
    const int lc = (t & 15) * 4;          // 0,4,...,60

    float acc[4][4];
#pragma unroll
    for (int i = 0; i < 4; ++i)
#pragma unroll
        for (int j = 0; j < 4; ++j) acc[i][j] = 0.f;

    const int nslab = (bj >> 1) + 1;      // L triangular: k <= bj*32+31

    for (int s = 0; s < nslab; ++s) {
        const int k0 = s * 64;
        float4 av = *(const float4*)&g_L[(size_t)(bi * 32 + lr) * NN + k0 + lc];
        float4 bv = *(const float4*)&g_L[(size_t)(bj * 32 + lr) * NN + k0 + lc];
        As[lc][lr] = av.x; As[lc + 1][lr] = av.y; As[lc + 2][lr] = av.z; As[lc + 3][lr] = av.w;
        Bs[lc][lr] = bv.x; Bs[lc + 1][lr] = bv.y; Bs[lc + 2][lr] = bv.z; Bs[lc + 3][lr] = bv.w;
        __syncthreads();

        const int kb = grp * 8;
#pragma unroll
        for (int kk = 0; kk < 8; ++kk) {
            float4 a  = *(const float4*)&As[kb + kk][ty * 4];
            float4 bb = *(const float4*)&Bs[kb + kk][tx * 4];
            acc[0][0] += a.x * bb.x; acc[0][1] += a.x * bb.y; acc[0][2] += a.x * bb.z; acc[0][3] += a.x * bb.w;
            acc[1][0] += a.y * bb.x; acc[1][1] += a.y * bb.y; acc[1][2] += a.y * bb.z; acc[1][3] += a.y * bb.w;
            acc[2][0] += a.z * bb.x; acc[2][1] += a.z * bb.y; acc[2][2] += a.z * bb.z; acc[2][3] += a.z * bb.w;
            acc[3][0] += a.w * bb.x; acc[3][1] += a.w * bb.y; acc[3][2] += a.w * bb.z; acc[3][3] += a.w * bb.w;
        }
        __syncthreads();
    }

    // two-stage 8-group reduction (overlay on SAB)
    float* red = &SAB[0][0][0];
    if (grp >= 4) {
        float* dst = red + ((grp - 4) * 64 + id64) * 16;
#pragma unroll
        for (int i = 0; i < 4; ++i)
#pragma unroll
            for (int j = 0; j < 4; ++j) dst[i * 4 + j] = acc[i][j];
    }
    __syncthreads();
    if (grp < 4) {
        const float* src = red + (grp * 64 + id64) * 16;
#pragma unroll
        for (int i = 0; i < 4; ++i)
#pragma unroll
            for (int j = 0; j < 4; ++j) acc[i][j] += src[i * 4 + j];
    }
    __syncthreads();
    if (grp >= 1 && grp < 4) {
        float* dst = red + ((grp - 1) * 64 + id64) * 16;
#pragma unroll
        for (int i = 0; i < 4; ++i)
#pragma unroll
            for (int j = 0; j < 4; ++j) dst[i * 4 + j] = acc[i][j];
    }
    __syncthreads();
    if (grp == 0) {
#pragma unroll
        for (int g = 0; g < 3; ++g) {
            const float* src = red + (g * 64 + id64) * 16;
#pragma unroll
            for (int i = 0; i < 4; ++i)
#pragma unroll
                for (int j = 0; j < 4; ++j) acc[i][j] += src[i * 4 + j];
        }

        const int R = bi * 32 + ty * 4;
        const int C = bj * 32 + tx * 4;
#pragma unroll
        for (int i = 0; i < 4; ++i) {
            float4 v; v.x = acc[i][0]; v.y = acc[i][1]; v.z = acc[i][2]; v.w = acc[i][3];
            *(float4*)&D[(size_t)(R + i) * NN + C] = v;
        }
        if (bi != bj) {   // mirror (D symmetric)
#pragma unroll
            for (int j = 0; j < 4; ++j) {
                float4 v; v.x = acc[0][j]; v.y = acc[1][j]; v.z = acc[2][j]; v.w = acc[3][j];
                *(float4*)&D[(size_t)(C + j) * NN + R] = v;
            }
        }
    }
}

// ---------------------------------------------------------------------------
extern "C" void kernel_launch(void* const* d_in, const int* in_sizes, int n_in,
                              void* d_out, int out_size) {
    const float* input = (const float*)d_in[0];
    const float* W0    = (const float*)d_in[1];
    const float* b0    = (const float*)d_in[2];
    const float* W1    = (const float*)d_in[3];
    const float* b1    = (const float*)d_in[4];
    const float* W2    = (const float*)d_in[5];
    const float* b2    = (const float*)d_in[6];
    const float* Wo    = (const float*)d_in[7];
    const float* bo    = (const float*)d_in[8];
    float* out = (float*)d_out;

    // Fused 3-layer MLP + L2 pre-stream of Wo's head
    mlp_all<<<MB, 256>>>(input, W0, b0, W1, b1, W2, Wo);

    // Dominant GEMV (537 MB) + L-building epilogue (last-arriver reduction)
    dim3 gv(KB_N, SPLITK);
    gemv_out<<<gv, 256>>>(Wo, b2, bo);

    // Pure GEMM: D = L L^T
    gemm_llt<<<GT, 512>>>(out);
}

// round 17
// speedup vs baseline: 1.1853x; 1.1853x over previous
#include <cuda_runtime.h>
#include <math.h>

// Problem constants
#define NN     512
#define HID    1024
#define OUTD   131328          // N + N*(N-1)/2
#define OUT4   (OUTD / 4)      // 32832 float4 columns
#define SPLITK 8
#define JCH    (HID / SPLITK)  // 128 rows of Wo per k-chunk
#define SI     16              // i-splits in fused MLP
#define MB     512             // blocks in fused MLP kernel (32 colgroups x SI)
#define GT     136             // lower-triangle 32x32 tiles (16*17/2)
#define PF     6               // L2-prefetch lines of Wo per MLP thread

// Device scratch (no allocation allowed). Referenced ONLY in device code.
__device__ float g_hp[3][SI][HID];       // per-layer split-i partials
__device__ float g_part[SPLITK][OUTD];   // split-K partial sums of big GEMV
__device__ float g_L[NN * NN];

// ---------------------------------------------------------------------------
// Software grid barrier (sense-reversal) — used ONLY by the 512-block MLP.
// ---------------------------------------------------------------------------
__device__ unsigned g_bar_ctr = 0;
__device__ volatile unsigned g_bar_gen = 0;

__device__ __forceinline__ void grid_barrier(unsigned nblocks) {
    __threadfence();
    __syncthreads();
    if (threadIdx.x == 0) {
        unsigned gen = g_bar_gen;
        if (atomicAdd(&g_bar_ctr, 1) == nblocks - 1) {
            g_bar_ctr = 0;
            __threadfence();
            g_bar_gen = gen + 1;
        } else {
            while (g_bar_gen == gen) __nanosleep(32);
        }
        __threadfence();
    }
    __syncthreads();
}

// ---------------------------------------------------------------------------
// Fused 3-layer MLP + L2 pre-stream of Wo's head (round-13 proven).
// ---------------------------------------------------------------------------
template <int IN>
__device__ __forceinline__ void mlp_partial(
    const float* __restrict__ xs, const float* __restrict__ W,
    int cg, int isp, float* __restrict__ outp, float sh[8][32]) {
    const int CHUNK = IN / SI;
    const int CH    = CHUNK / 8;
    const int lane  = threadIdx.x & 31;
    const int w     = threadIdx.x >> 5;
    const int j     = cg * 32 + lane;
    const int base  = isp * CHUNK;
    const int i0    = w * CH;

    float acc = 0.f;
#pragma unroll
    for (int i = 0; i < CH; ++i) {
        acc += xs[i0 + i] * __ldg(&W[(size_t)(base + i0 + i) * 1024 + j]);
    }
    sh[w][lane] = acc;
    __syncthreads();
    if (w == 0) {
        float s = 0.f;
#pragma unroll
        for (int q = 0; q < 8; ++q) s += sh[q][lane];
        outp[j] = s;
    }
    __syncthreads();
}

__global__ void __launch_bounds__(256)
mlp_all(const float* __restrict__ x,
        const float* __restrict__ W0, const float* __restrict__ b0,
        const float* __restrict__ W1, const float* __restrict__ b1,
        const float* __restrict__ W2, const float* __restrict__ Wo) {
    __shared__ float sh[8][32];
    __shared__ float xs[HID / SI];

    const int cg  = blockIdx.x & 31;
    const int isp = blockIdx.x >> 5;

    // Pre-stream head of Wo into L2 (rides idle DRAM BW; ~100MB).
    {
        const size_t tg = (size_t)blockIdx.x * 256 + threadIdx.x;
#pragma unroll
        for (int p = 0; p < PF; ++p) {
            const float* a = Wo + (tg * PF + p) * 32;
            asm volatile("prefetch.global.L2 [%0];" :: "l"(a));
        }
    }

    // ---- layer 0: IN=512 ----
    {
        const int CHUNK = 512 / SI;
        for (int t = threadIdx.x; t < CHUNK; t += 256) xs[t] = x[isp * CHUNK + t];
        __syncthreads();
        mlp_partial<512>(xs, W0, cg, isp, g_hp[0][isp], sh);
    }
    grid_barrier(MB);

    // ---- layer 1: IN=1024 ----
    {
        const int CHUNK = HID / SI;
        for (int t = threadIdx.x; t < CHUNK; t += 256) {
            const int g = isp * CHUNK + t;
            float s = __ldg(&b0[g]);
#pragma unroll
            for (int q = 0; q < SI; ++q) s += g_hp[0][q][g];
            xs[t] = tanhf(s);
        }
        __syncthreads();
        mlp_partial<1024>(xs, W1, cg, isp, g_hp[1][isp], sh);
    }
    grid_barrier(MB);

    // ---- layer 2: IN=1024 ----
    {
        const int CHUNK = HID / SI;
        for (int t = threadIdx.x; t < CHUNK; t += 256) {
            const int g = isp * CHUNK + t;
            float s = __ldg(&b1[g]);
#pragma unroll
            for (int q = 0; q < SI; ++q) s += g_hp[1][q][g];
            xs[t] = tanhf(s);
        }
        __syncthreads();
        mlp_partial<1024>(xs, W2, cg, isp, g_hp[2][isp], sh);
    }
}

// ---------------------------------------------------------------------------
// Big GEMV, split-K (round-13 proven core; head of Wo L2-hot).
// grid = (129, SPLITK), block = 256.
// ---------------------------------------------------------------------------
__global__ void gemv_out(const float* __restrict__ Wo,
                         const float* __restrict__ b2) {
    const int chunk = blockIdx.y;

    __shared__ float hs[JCH];
    if (threadIdx.x < JCH) {
        const int t = chunk * JCH + threadIdx.x;
        float s = __ldg(&b2[t]);
#pragma unroll
        for (int q = 0; q < SI; ++q) s += g_hp[2][q][t];
        hs[threadIdx.x] = tanhf(s);
    }
    __syncthreads();

    const int k4 = blockIdx.x * blockDim.x + threadIdx.x;
    if (k4 >= OUT4) return;

    const float4* W4 = (const float4*)Wo + (size_t)chunk * JCH * OUT4;
    float ax = 0.f, ay = 0.f, az = 0.f, aw = 0.f;

#pragma unroll 8
    for (int j = 0; j < JCH; ++j) {
        float4 wv = __ldcs(&W4[(size_t)j * OUT4 + k4]);
        float  hj = hs[j];
        ax += hj * wv.x;
        ay += hj * wv.y;
        az += hj * wv.z;
        aw += hj * wv.w;
    }

    float4 r; r.x = ax; r.y = ay; r.z = az; r.w = aw;
    ((float4*)g_part[chunk])[k4] = r;
}

// ---------------------------------------------------------------------------
// build_L: standalone, wide (512 blocks x 256 thr, 2 elements/thread).
// o[k] = bo[k] + sum_q part[q][k]; diag=exp, upper=0. Partials are L2-hot.
// ---------------------------------------------------------------------------
__global__ void __launch_bounds__(256)
build_L(const float* __restrict__ bo) {
    int idx = blockIdx.x * 256 + threadIdx.x;
#pragma unroll
    for (int rep = 0; rep < 2; ++rep, idx += 512 * 256) {
        const int r = idx >> 9;
        const int c = idx & 511;
        float v;
        if (c > r) {
            v = 0.f;
        } else {
            const int k = (c < r) ? (NN + (r * (r - 1)) / 2 + c) : r;
            float s = __ldg(&bo[k]);
#pragma unroll
            for (int q = 0; q < SPLITK; ++q) s += g_part[q][k];
            v = (c < r) ? s : expf(s);
        }
        g_L[idx] = v;
    }
}

// ---------------------------------------------------------------------------
// Pure GEMM: D = L * L^T. Kernel boundary is the sync (gaps ~0 under graph).
// grid = GT=136 lower-triangle tiles, block = 512, triangular-k,
// 4x4 microtiles, 8-way k-split, two-stage smem reduction.
// ---------------------------------------------------------------------------
__global__ void __launch_bounds__(512)
gemm_llt(float* __restrict__ D) {
    __shared__ float SAB[2][64][36];   // As/Bs; reduction buffer overlaid

    const int b = blockIdx.x;
    const int t = threadIdx.x;         // 0..511

    // linear block id -> (bi, bj), bj <= bi
    int bi = (int)((sqrtf(8.f * b + 1.f) - 1.f) * 0.5f);
    while ((bi + 1) * (bi + 2) / 2 <= b) ++bi;
    while (bi * (bi + 1) / 2 > b) --bi;
    const int bj = b - bi * (bi + 1) / 2;

    float (*As)[36] = SAB[0];
    float (*Bs)[36] = SAB[1];

    const int grp  = t >> 6;              // 0..7: k-groups of 8
    const int id64 = t & 63;
    const int tx   = id64 & 7;
    const int ty   = id64 >> 3;

    const int lr = t >> 4;                // 0..31
    const int lc = (t & 15) * 4;          // 0,4,...,60

    float acc[4][4];
#pragma unroll
    for (int i = 0; i < 4; ++i)
#pragma unroll
        for (int j = 0; j < 4; ++j) acc[i][j] = 0.f;

    const int nslab = (bj >> 1) + 1;      // L triangular: k <= bj*32+31

    for (int s = 0; s < nslab; ++s) {
        const int k0 = s * 64;
        float4 av = *(const float4*)&g_L[(size_t)(bi * 32 + lr) * NN + k0 + lc];
        float4 bv = *(const float4*)&g_L[(size_t)(bj * 32 + lr) * NN + k0 + lc];
        As[lc][lr] = av.x; As[lc + 1][lr] = av.y; As[lc + 2][lr] = av.z; As[lc + 3][lr] = av.w;
        Bs[lc][lr] = bv.x; Bs[lc + 1][lr] = bv.y; Bs[lc + 2][lr] = bv.z; Bs[lc + 3][lr] = bv.w;
        __syncthreads();

        const int kb = grp * 8;
#pragma unroll
        for (int kk = 0; kk < 8; ++kk) {
            float4 a  = *(const float4*)&As[kb + kk][ty * 4];
            float4 bb = *(const float4*)&Bs[kb + kk][tx * 4];
            acc[0][0] += a.x * bb.x; acc[0][1] += a.x * bb.y; acc[0][2] += a.x * bb.z; acc[0][3] += a.x * bb.w;
            acc[1][0] += a.y * bb.x; acc[1][1] += a.y * bb.y; acc[1][2] += a.y * bb.z; acc[1][3] += a.y * bb.w;
            acc[2][0] += a.z * bb.x; acc[2][1] += a.z * bb.y; acc[2][2] += a.z * bb.z; acc[2][3] += a.z * bb.w;
            acc[3][0] += a.w * bb.x; acc[3][1] += a.w * bb.y; acc[3][2] += a.w * bb.z; acc[3][3] += a.w * bb.w;
        }
        __syncthreads();
    }

    // two-stage 8-group reduction (overlay on SAB)
    float* red = &SAB[0][0][0];
    if (grp >= 4) {
        float* dst = red + ((grp - 4) * 64 + id64) * 16;
#pragma unroll
        for (int i = 0; i < 4; ++i)
#pragma unroll
            for (int j = 0; j < 4; ++j) dst[i * 4 + j] = acc[i][j];
    }
    __syncthreads();
    if (grp < 4) {
        const float* src = red + (grp * 64 + id64) * 16;
#pragma unroll
        for (int i = 0; i < 4; ++i)
#pragma unroll
            for (int j = 0; j < 4; ++j) acc[i][j] += src[i * 4 + j];
    }
    __syncthreads();
    if (grp >= 1 && grp < 4) {
        float* dst = red + ((grp - 1) * 64 + id64) * 16;
#pragma unroll
        for (int i = 0; i < 4; ++i)
#pragma unroll
            for (int j = 0; j < 4; ++j) dst[i * 4 + j] = acc[i][j];
    }
    __syncthreads();
    if (grp == 0) {
#pragma unroll
        for (int g = 0; g < 3; ++g) {
            const float* src = red + (g * 64 + id64) * 16;
#pragma unroll
            for (int i = 0; i < 4; ++i)
#pragma unroll
                for (int j = 0; j < 4; ++j) acc[i][j] += src[i * 4 + j];
        }

        const int R = bi * 32 + ty * 4;
        const int C = bj * 32 + tx * 4;
#pragma unroll
        for (int i = 0; i < 4; ++i) {
            float4 v; v.x = acc[i][0]; v.y = acc[i][1]; v.z = acc[i][2]; v.w = acc[i][3];
            *(float4*)&D[(size_t)(R + i) * NN + C] = v;
        }
        if (bi != bj) {   // mirror (D symmetric)
#pragma unroll
            for (int j = 0; j < 4; ++j) {
                float4 v; v.x = acc[0][j]; v.y = acc[1][j]; v.z = acc[2][j]; v.w = acc[3][j];
                *(float4*)&D[(size_t)(C + j) * NN + R] = v;
            }
        }
    }
}

// ---------------------------------------------------------------------------
extern "C" void kernel_launch(void* const* d_in, const int* in_sizes, int n_in,
                              void* d_out, int out_size) {
    const float* input = (const float*)d_in[0];
    const float* W0    = (const float*)d_in[1];
    const float* b0    = (const float*)d_in[2];
    const float* W1    = (const float*)d_in[3];
    const float* b1    = (const float*)d_in[4];
    const float* W2    = (const float*)d_in[5];
    const float* b2    = (const float*)d_in[6];
    const float* Wo    = (const float*)d_in[7];
    const float* bo    = (const float*)d_in[8];
    float* out = (float*)d_out;

    // Fused 3-layer MLP + L2 pre-stream of Wo's head
    mlp_all<<<MB, 256>>>(input, W0, b0, W1, b1, W2, Wo);

    // Dominant GEMV over Wo (537 MB stream; head ~100MB L2-hot)
    dim3 gv((OUT4 + 255) / 256, SPLITK);
    gemv_out<<<gv, 256>>>(Wo, b2);

    // L assembly (wide, standalone) then pure GEMM — gaps ~0 under graph
    build_L<<<512, 256>>>(bo);
    gemm_llt<<<GT, 512>>>(out);
}